// round 9
// baseline (speedup 1.0000x reference)
#include <cuda_runtime.h>
#include <cstdint>

// Problem constants — 2 independent batch groups x 64 CTAs = 128 SMs used
#define NGRP      2
#define GCTAS     64     // CTAs per group (all 128 co-resident on 148 SMs)
#define NCTA      (NGRP * GCTAS)
#define NTHREADS  256    // 8 warps — proven best shape
#define BB        16     // total batch
#define GB        8      // batches per group
#define TT        1024   // time steps
#define DD        768    // hidden dim
#define NGATES    4
#define DPC       12     // d-columns per CTA (64*12 = 768)
#define GC        48     // gate columns per CTA (interleaved: gc = dl*4 + gate)
#define NSLICE    16     // k-slices = 8 warps x 2 half-warps
#define KS        48     // k per slice (16*48 = 768)
#define KS2       24     // packed f32x2 k-pairs per slice
#define REDPITCH  384    // floats per slice spill row (8 b x 48 gc)
#define PRODS     8      // producer CTAs per warp (96 k-cols / 12 d-per-CTA)

// Global exchange state (device globals: no allocation anywhere)
__device__ __align__(16) float    g_hbuf[2][BB * DD];
__device__ unsigned               g_flags[NCTA];   // per-CTA monotonic step flag

static __device__ __forceinline__ unsigned long long pack2(float x, float y) {
    unsigned long long r;
    asm("mov.b64 %0, {%1, %2};" : "=l"(r) : "f"(x), "f"(y));
    return r;
}
static __device__ __forceinline__ void fma2(unsigned long long& d,
                                            unsigned long long a,
                                            unsigned long long b) {
    // Packed dual-FMA (Blackwell f32x2) — 2x FFMA throughput vs scalar.
    asm("fma.rn.f32x2 %0, %1, %2, %0;" : "+l"(d) : "l"(a), "l"(b));
}
static __device__ __forceinline__ float2 unpack2(unsigned long long v) {
    float lo, hi;
    asm("mov.b64 {%0, %1}, %2;" : "=f"(lo), "=f"(hi) : "l"(v));
    return make_float2(lo, hi);
}

// Zero the flags before each run (graph replays reuse device globals).
__global__ void rnn_reset_kernel() {
    if (threadIdx.x < NCTA) g_flags[threadIdx.x] = 0u;
}

__global__ void __launch_bounds__(NTHREADS, 1)
rnn_persistent_kernel(const float* __restrict__ states,
                      const float* __restrict__ Wx,
                      const float* __restrict__ R,
                      const float* __restrict__ bias,
                      float* __restrict__ out)
{
    // Dynamic smem = 48KB: h panel (24KB, WARP-PRIVATE column slices) + red
    // spill scratch (24KB). No aliasing -> no syncs around the GEMM at all.
    extern __shared__ float smem[];
    float* h_sm = smem;                        // [GB][DD]           = 6144 floats
    float* red  = smem + GB * DD;              // [NSLICE][REDPITCH] = 6144 floats

    const int tid = threadIdx.x;
    const int grp = blockIdx.x >> 6;     // batch group 0/1
    const int cta = blockIdx.x & 63;     // CTA within group
    const int w   = tid >> 5;            // warp id (0..7)
    const int l   = tid & 31;            // lane
    const int hw  = l >> 4;              // half-warp -> k sub-slice
    const int c   = l & 15;              // column index (0..15)
    const int sl  = (w << 1) | hw;       // k-slice id (0..15)
    const int kb  = sl * KS;             // k base for this slice
    const int gcA = c;                   // 3 interleaved cols: gg = gc&3, dl = gc>>2
    const int gcB = c + 16;
    const int gcC = c + 32;
    const int d0  = cta * DPC;

    // ---- One-time: R slices for all 3 columns into registers (k-pair packed).
    unsigned long long RA[KS2], RB[KS2], RC[KS2];   // 144 registers
    {
        const float* RgA = R + (size_t)(gcA & 3) * DD * DD + (size_t)(d0 + (gcA >> 2));
        const float* RgB = R + (size_t)(gcB & 3) * DD * DD + (size_t)(d0 + (gcB >> 2));
        const float* RgC = R + (size_t)(gcC & 3) * DD * DD + (size_t)(d0 + (gcC >> 2));
        #pragma unroll
        for (int j = 0; j < KS2; ++j) {
            RA[j] = pack2(RgA[(size_t)(kb + 2 * j) * DD], RgA[(size_t)(kb + 2 * j + 1) * DD]);
            RB[j] = pack2(RgB[(size_t)(kb + 2 * j) * DD], RgB[(size_t)(kb + 2 * j + 1) * DD]);
            RC[j] = pack2(RgC[(size_t)(kb + 2 * j) * DD], RgC[(size_t)(kb + 2 * j + 1) * DD]);
        }
    }

    // ---- One-time: per-cell state (c) and t=0 output row. 96 cell threads.
    float c_state = 0.f;
    int gb = 0, cbl = 0, cd = 0;                  // global batch, local batch, local d
    if (tid < GB * DPC) {                         // 96 cells
        cbl = tid / DPC;
        cd  = tid - cbl * DPC;
        gb  = grp * GB + cbl;
        const int d = d0 + cd;
        const float h0 = states[(size_t)(0 * BB + gb) * DD + d];
        c_state        = states[(size_t)(1 * BB + gb) * DD + d];
        out[((size_t)(0 * BB + gb) * (TT + 1) + 0) * DD + d] = h0;
        out[((size_t)(1 * BB + gb) * (TT + 1) + 0) * DD + d] = c_state;
    }

    // My producer flags: warp w consumes k-cols [w*96, w*96+96) produced by
    // group CTAs w*8 .. w*8+7. Across the CTA's 8 warps this covers all 64
    // group flags (load-bearing for the double-buffer safety argument).
    volatile unsigned* myflags = (volatile unsigned*)&g_flags[grp * GCTAS + (w << 3)];

    // ---- Main recurrence ----
    for (int t = 0; t < TT; ++t) {
        // Phase 0: per-warp producer wait. flag[c] >= t means CTA c finished
        // step t-1 entirely: wrote h(t) AND finished reading h(t-1).
        if (t > 0) {
            if (l < PRODS) {
                volatile unsigned* f = myflags + l;
                while (*f < (unsigned)t) { }
            }
            __syncwarp();
            __threadfence();               // acquire: h loads below see h(t)
        }

        // Phase 1: issue Wx(t) + bias loads early (consumed in cell phase).
        float wxi = 0.f, wxf = 0.f, wxz = 0.f, wxo = 0.f;
        if (tid < GB * DPC) {
            const int d = d0 + cd;
            const float* wp = Wx + ((size_t)gb * TT + t) * (NGATES * DD) + d;
            wxi = wp[0 * DD] + bias[0 * DD + d];
            wxf = wp[1 * DD] + bias[1 * DD + d];
            wxz = wp[2 * DD] + bias[2 * DD + d];
            wxo = wp[3 * DD] + bias[3 * DD + d];
        }

        // Phase 2: WARP-LOCAL h slice load — warp w owns k-cols [w*96,w*96+96)
        // of h_sm exclusively (writes here, reads below; no other warp touches
        // them). 192 float4 per warp -> 6 per lane.
        {
            const float4* s4 = (const float4*)((t == 0) ? states : g_hbuf[t & 1])
                               + (size_t)grp * GB * (DD / 4);
            float4* d4 = (float4*)h_sm;
            #pragma unroll
            for (int r = 0; r < 6; ++r) {
                const int local = r * 32 + l;          // 0..191
                const int b  = local / 24;             // 24 float4 per k-slice row
                const int kq = local - b * 24;
                const int idx = b * (DD / 4) + w * 24 + kq;
                d4[idx] = s4[idx];
            }
            __syncwarp();
        }

        // Phase 3: GEMM. Half-warp owns 48-k slice; lane owns 3 gate columns.
        // One LDS.128 (4 h, half-warp broadcast) feeds 6 FFMA2.
        unsigned long long accA[GB], accB[GB], accC[GB];   // 48 registers
        #pragma unroll
        for (int b = 0; b < GB; ++b) { accA[b] = 0ull; accB[b] = 0ull; accC[b] = 0ull; }
        {
            const float* hk = h_sm + kb;
            #pragma unroll
            for (int j = 0; j < KS2; j += 2) {        // 12 iters, 4 k each
                #pragma unroll
                for (int b = 0; b < GB; ++b) {
                    const ulonglong2 hh =
                        *(const ulonglong2*)(hk + (size_t)b * DD + 2 * j);
                    fma2(accA[b], hh.x, RA[j]);
                    fma2(accA[b], hh.y, RA[j + 1]);
                    fma2(accB[b], hh.x, RB[j]);
                    fma2(accB[b], hh.y, RB[j + 1]);
                    fma2(accC[b], hh.x, RC[j]);
                    fma2(accC[b], hh.y, RC[j + 1]);
                }
            }
        }

        // Phase 4: spill per-slice partials red[sl][b*48+gc] (fold even/odd k).
        // red is disjoint from h_sm and slice-private -> no sync needed first.
        {
            float* rw = red + (size_t)sl * REDPITCH;
            #pragma unroll
            for (int b = 0; b < GB; ++b) {
                const float2 vA = unpack2(accA[b]);
                const float2 vB = unpack2(accB[b]);
                const float2 vC = unpack2(accC[b]);
                rw[b * GC + gcA] = vA.x + vA.y;
                rw[b * GC + gcB] = vB.x + vB.y;
                rw[b * GC + gcC] = vC.x + vC.y;
            }
        }
        __syncthreads();   // S3: all spills visible (also: all warps observed
                           // all 64 producer flags >= t by this point)

        // Phase 5+6 fused: cell threads reduce their 4 gates (one float4 per
        // slice, interleaved gc) and run the LSTM update.
        float hn = 0.f, cn = 0.f;
        if (tid < GB * DPC) {
            const int off = cbl * GC + cd * 4;        // gates i,f,z,o contiguous
            float4 g = make_float4(0.f, 0.f, 0.f, 0.f);
            #pragma unroll
            for (int ss = 0; ss < NSLICE; ++ss) {
                const float4 p = *(const float4*)(red + ss * REDPITCH + off);
                g.x += p.x; g.y += p.y; g.z += p.z; g.w += p.w;
            }
            const float gi = g.x + wxi;
            const float gf = g.y + wxf;
            const float gz = g.z + wxz;
            const float go = g.w + wxo;
            const float i_ = 1.f / (1.f + __expf(-gi));
            const float f_ = 1.f / (1.f + __expf(-gf));
            const float z_ = tanhf(gz);
            const float o_ = 1.f / (1.f + __expf(-go));
            cn = f_ * c_state + i_ * z_;
            hn = o_ * tanhf(cn);
            c_state = cn;
            g_hbuf[(t + 1) & 1][(size_t)gb * DD + d0 + cd] = hn;   // exchange
        }

        // Phase 7: publish. S_flag orders all cell h-writes (and red reads)
        // before the flag store; consumers poll the flag directly.
        __syncthreads();                   // S_flag
        if (tid == 0) {
            __threadfence();               // make h(t+1) writes GPU-visible
            ((volatile unsigned*)g_flags)[grp * GCTAS + cta] = (unsigned)(t + 1);
        }
        // Off-critical-path: out[] rows for t+1 (never read cross-CTA).
        if (tid < GB * DPC) {
            const int d = d0 + cd;
            out[((size_t)(0 * BB + gb) * (TT + 1) + (t + 1)) * DD + d] = hn;
            out[((size_t)(1 * BB + gb) * (TT + 1) + (t + 1)) * DD + d] = cn;
        }
        // No trailing CTA barrier: next step's per-warp poll is the sync.
    }
}

extern "C" void kernel_launch(void* const* d_in, const int* in_sizes, int n_in,
                              void* d_out, int out_size)
{
    const float* states = (const float*)d_in[0];  // [2,16,1,768]
    const float* Wx     = (const float*)d_in[1];  // [16,1024,4,1,768]
    const float* R      = (const float*)d_in[2];  // [4,1,768,768]
    const float* bias   = (const float*)d_in[3];  // [4,1,768]
    float*       out    = (float*)d_out;          // [2,16,1025,1,768]

    const size_t smem_bytes = (size_t)(GB * DD + NSLICE * REDPITCH) * sizeof(float); // 48KB

    rnn_reset_kernel<<<1, 128>>>();
    rnn_persistent_kernel<<<NCTA, NTHREADS, smem_bytes>>>(states, Wx, R, bias, out);
}

// round 10
// speedup vs baseline: 2.1681x; 2.1681x over previous
#include <cuda_runtime.h>
#include <cstdint>

// Problem constants — 2 independent batch groups x 64 CTAs = 128 SMs used
#define NGRP      2
#define GCTAS     64     // CTAs per group (all 128 co-resident on 148 SMs)
#define NCTA      (NGRP * GCTAS)
#define NTHREADS  256    // 8 warps — proven best shape
#define BB        16     // total batch
#define GB        8      // batches per group
#define TT        1024   // time steps
#define DD        768    // hidden dim
#define NGATES    4
#define DPC       12     // d-columns per CTA (64*12 = 768)
#define GC        48     // gate columns per CTA (interleaved: gc = dl*4 + gate)
#define NSLICE    16     // k-slices = 8 warps x 2 half-warps
#define KS        48     // k per slice (16*48 = 768)
#define KS2       24     // packed f32x2 k-pairs per slice
#define NW        8      // warps (fold: 16 slices -> 8 spill rows)
#define REDPITCH  384    // floats per spill row (8 b x 48 gc)

// Global exchange state (device globals: no allocation anywhere)
__device__ __align__(16) float    g_hbuf[2][BB * DD];
__device__ unsigned               g_ctr[NGRP * 32];   // 128B-padded per group

static __device__ __forceinline__ unsigned long long pack2(float x, float y) {
    unsigned long long r;
    asm("mov.b64 %0, {%1, %2};" : "=l"(r) : "f"(x), "f"(y));
    return r;
}
static __device__ __forceinline__ void fma2(unsigned long long& d,
                                            unsigned long long a,
                                            unsigned long long b) {
    // Packed dual-FMA (Blackwell f32x2) — 2x FFMA throughput vs scalar.
    asm("fma.rn.f32x2 %0, %1, %2, %0;" : "+l"(d) : "l"(a), "l"(b));
}
static __device__ __forceinline__ float2 unpack2(unsigned long long v) {
    float lo, hi;
    asm("mov.b64 {%0, %1}, %2;" : "=f"(lo), "=f"(hi) : "l"(v));
    return make_float2(lo, hi);
}

// Zero the barrier counters before each run (graph replays reuse device globals).
__global__ void rnn_reset_kernel() {
    if (threadIdx.x < NGRP * 32) g_ctr[threadIdx.x] = 0u;
}

__global__ void __launch_bounds__(NTHREADS, 1)
rnn_persistent_kernel(const float* __restrict__ states,
                      const float* __restrict__ Wx,
                      const float* __restrict__ R,
                      const float* __restrict__ bias,
                      float* __restrict__ out)
{
    // Dynamic smem = 36KB: h panel (24KB, warp-private column slices) + red
    // spill scratch (12KB, DISJOINT -> no sync between GEMM and spill).
    extern __shared__ float smem[];
    float* h_sm = smem;                        // [GB][DD]       = 6144 floats
    float* red  = smem + GB * DD;              // [NW][REDPITCH] = 3072 floats

    const int tid = threadIdx.x;
    const int grp = blockIdx.x >> 6;     // batch group 0/1
    const int cta = blockIdx.x & 63;     // CTA within group
    const int w   = tid >> 5;            // warp id (0..7)
    const int l   = tid & 31;            // lane
    const int hw  = l >> 4;              // half-warp -> k sub-slice
    const int c   = l & 15;              // column index (0..15)
    const int sl  = (w << 1) | hw;       // k-slice id (0..15)
    const int kb  = sl * KS;             // k base for this slice
    const int gcA = c;                   // 3 interleaved cols: gg = gc&3, dl = gc>>2
    const int gcB = c + 16;
    const int gcC = c + 32;
    const int d0  = cta * DPC;

    // ---- One-time: R slices for all 3 columns into registers (k-pair packed).
    unsigned long long RA[KS2], RB[KS2], RC[KS2];   // 144 registers
    {
        const float* RgA = R + (size_t)(gcA & 3) * DD * DD + (size_t)(d0 + (gcA >> 2));
        const float* RgB = R + (size_t)(gcB & 3) * DD * DD + (size_t)(d0 + (gcB >> 2));
        const float* RgC = R + (size_t)(gcC & 3) * DD * DD + (size_t)(d0 + (gcC >> 2));
        #pragma unroll
        for (int j = 0; j < KS2; ++j) {
            RA[j] = pack2(RgA[(size_t)(kb + 2 * j) * DD], RgA[(size_t)(kb + 2 * j + 1) * DD]);
            RB[j] = pack2(RgB[(size_t)(kb + 2 * j) * DD], RgB[(size_t)(kb + 2 * j + 1) * DD]);
            RC[j] = pack2(RgC[(size_t)(kb + 2 * j) * DD], RgC[(size_t)(kb + 2 * j + 1) * DD]);
        }
    }

    // ---- One-time: per-cell state (c) and t=0 output row. 96 cell threads.
    float c_state = 0.f;
    int gb = 0, cbl = 0, cd = 0;                  // global batch, local batch, local d
    if (tid < GB * DPC) {                         // 96 cells
        cbl = tid / DPC;
        cd  = tid - cbl * DPC;
        gb  = grp * GB + cbl;
        const int d = d0 + cd;
        const float h0 = states[(size_t)(0 * BB + gb) * DD + d];
        c_state        = states[(size_t)(1 * BB + gb) * DD + d];
        out[((size_t)(0 * BB + gb) * (TT + 1) + 0) * DD + d] = h0;
        out[((size_t)(1 * BB + gb) * (TT + 1) + 0) * DD + d] = c_state;
    }

    volatile unsigned* ctr = &g_ctr[grp * 32];

    // ---- Wx(0)+bias preload (subsequent steps prefetched during barrier wait).
    float wxi = 0.f, wxf = 0.f, wxz = 0.f, wxo = 0.f;
    if (tid < GB * DPC) {
        const int d = d0 + cd;
        const float* wp = Wx + ((size_t)gb * TT + 0) * (NGATES * DD) + d;
        wxi = wp[0 * DD] + bias[0 * DD + d];
        wxf = wp[1 * DD] + bias[1 * DD + d];
        wxz = wp[2 * DD] + bias[2 * DD + d];
        wxo = wp[3 * DD] + bias[3 * DD + d];
    }

    // ---- Main recurrence ----
    for (int t = 0; t < TT; ++t) {
        // Phase 2: WARP-LOCAL h slice load — warp w owns k-cols [w*96,w*96+96)
        // of h_sm exclusively. 192 float4 per warp -> 6 per lane.
        {
            const float4* s4 = (const float4*)((t == 0) ? states : g_hbuf[t & 1])
                               + (size_t)grp * GB * (DD / 4);
            float4* d4 = (float4*)h_sm;
            #pragma unroll
            for (int r = 0; r < 6; ++r) {
                const int local = r * 32 + l;          // 0..191
                const int b  = local / 24;             // 24 float4 per k-slice row
                const int kq = local - b * 24;
                const int idx = b * (DD / 4) + w * 24 + kq;
                d4[idx] = s4[idx];
            }
            __syncwarp();
        }

        // Phase 3: GEMM. Half-warp owns 48-k slice; lane owns 3 gate columns.
        // One LDS.128 (4 h, half-warp broadcast) feeds 6 FFMA2.
        unsigned long long accA[GB], accB[GB], accC[GB];   // 48 registers
        #pragma unroll
        for (int b = 0; b < GB; ++b) { accA[b] = 0ull; accB[b] = 0ull; accC[b] = 0ull; }
        {
            const float* hk = h_sm + kb;
            #pragma unroll
            for (int j = 0; j < KS2; j += 2) {        // 12 iters, 4 k each
                #pragma unroll
                for (int b = 0; b < GB; ++b) {
                    const ulonglong2 hh =
                        *(const ulonglong2*)(hk + (size_t)b * DD + 2 * j);
                    fma2(accA[b], hh.x, RA[j]);
                    fma2(accA[b], hh.y, RA[j + 1]);
                    fma2(accB[b], hh.x, RB[j]);
                    fma2(accB[b], hh.y, RB[j + 1]);
                    fma2(accC[b], hh.x, RC[j]);
                    fma2(accC[b], hh.y, RC[j + 1]);
                }
            }
        }

        // Phase 4: shuffle-fold the warp's two half-warp slices (lane l and
        // l+16 hold the same (b,gc) for slices 2w / 2w+1), then lanes 0-15
        // spill ONE row per warp. red disjoint from h_sm -> no pre-sync.
        {
            float* rw = red + (size_t)w * REDPITCH;
            #pragma unroll
            for (int b = 0; b < GB; ++b) {
                const float2 vA = unpack2(accA[b]);
                const float2 vB = unpack2(accB[b]);
                const float2 vC = unpack2(accC[b]);
                float sA = vA.x + vA.y;
                float sB = vB.x + vB.y;
                float sC = vC.x + vC.y;
                sA += __shfl_down_sync(0xffffffffu, sA, 16);
                sB += __shfl_down_sync(0xffffffffu, sB, 16);
                sC += __shfl_down_sync(0xffffffffu, sC, 16);
                if (hw == 0) {
                    rw[b * GC + gcA] = sA;
                    rw[b * GC + gcB] = sB;
                    rw[b * GC + gcC] = sC;
                }
            }
        }
        __syncthreads();   // S3: all spills visible

        // Phase 5+6 fused: cell threads reduce their 4 gates (one float4 per
        // warp-row, interleaved gc) and run the LSTM update.
        float hn = 0.f, cn = 0.f;
        if (tid < GB * DPC) {
            const int off = cbl * GC + cd * 4;        // gates i,f,z,o contiguous
            float4 g = make_float4(0.f, 0.f, 0.f, 0.f);
            #pragma unroll
            for (int ww = 0; ww < NW; ++ww) {
                const float4 p = *(const float4*)(red + ww * REDPITCH + off);
                g.x += p.x; g.y += p.y; g.z += p.z; g.w += p.w;
            }
            const float gi = g.x + wxi;
            const float gf = g.y + wxf;
            const float gz = g.z + wxz;
            const float go = g.w + wxo;
            const float i_ = 1.f / (1.f + __expf(-gi));
            const float f_ = 1.f / (1.f + __expf(-gf));
            const float z_ = tanhf(gz);
            const float o_ = 1.f / (1.f + __expf(-go));
            cn = f_ * c_state + i_ * z_;
            hn = o_ * tanhf(cn);
            c_state = cn;
            g_hbuf[(t + 1) & 1][(size_t)gb * DD + d0 + cd] = hn;   // exchange
        }

        // Phase 7: PER-GROUP grid barrier (64 arrivals) — single monotonic
        // counter, ONE arriver + ONE poller per CTA (only proven-fast shape).
        __syncthreads();                   // S_flag: h writes issued by all cells
        if (tid == 0) {
            __threadfence();               // make h writes GPU-visible
            atomicAdd((unsigned*)ctr, 1u);
        }
        // Off-critical-path while waiting: out[] rows for t+1, and Wx(t+2)
        // prefetch (hides the DRAM stream entirely behind the barrier).
        if (tid < GB * DPC) {
            const int d = d0 + cd;
            out[((size_t)(0 * BB + gb) * (TT + 1) + (t + 1)) * DD + d] = hn;
            out[((size_t)(1 * BB + gb) * (TT + 1) + (t + 1)) * DD + d] = cn;
            if (t + 1 < TT) {
                const float* wp = Wx + ((size_t)gb * TT + (t + 1)) * (NGATES * DD) + d;
                wxi = wp[0 * DD] + bias[0 * DD + d];
                wxf = wp[1 * DD] + bias[1 * DD + d];
                wxz = wp[2 * DD] + bias[2 * DD + d];
                wxo = wp[3 * DD] + bias[3 * DD + d];
            }
        }
        if (tid == 0) {
            const unsigned target = (unsigned)(GCTAS) * (unsigned)(t + 1);
            while (*ctr < target) { }
            __threadfence();               // acquire
        }
        __syncthreads();                   // release whole CTA
    }
}

extern "C" void kernel_launch(void* const* d_in, const int* in_sizes, int n_in,
                              void* d_out, int out_size)
{
    const float* states = (const float*)d_in[0];  // [2,16,1,768]
    const float* Wx     = (const float*)d_in[1];  // [16,1024,4,1,768]
    const float* R      = (const float*)d_in[2];  // [4,1,768,768]
    const float* bias   = (const float*)d_in[3];  // [4,1,768]
    float*       out    = (float*)d_out;          // [2,16,1025,1,768]

    const size_t smem_bytes = (size_t)(GB * DD + NW * REDPITCH) * sizeof(float); // 36KB

    rnn_reset_kernel<<<1, 64>>>();
    rnn_persistent_kernel<<<NCTA, NTHREADS, smem_bytes>>>(states, Wx, R, bias, out);
}

// round 11
// speedup vs baseline: 2.4180x; 1.1153x over previous
#include <cuda_runtime.h>
#include <cstdint>

// Problem constants — 2 independent batch groups x 64 CTAs = 128 SMs used
#define NGRP      2
#define GCTAS     64     // CTAs per group (all 128 co-resident on 148 SMs)
#define NCTA      (NGRP * GCTAS)
#define NTHREADS  256    // 8 warps — proven best shape
#define BB        16     // total batch
#define GB        8      // batches per group
#define TT        1024   // time steps
#define DD        768    // hidden dim
#define NGATES    4
#define DPC       12     // d-columns per CTA (64*12 = 768)
#define GC        48     // gate columns per CTA (interleaved: gc = dl*4 + gate)
#define NSLICE    16     // k-slices = 8 warps x 2 half-warps
#define KS        48     // k per slice (16*48 = 768)
#define KS2       24     // packed f32x2 k-pairs per slice
#define REDPITCH  384    // floats per slice spill row (8 b x 48 gc)

// Global exchange state (device globals: no allocation anywhere)
__device__ __align__(16) float    g_hbuf[2][BB * DD];
__device__ unsigned               g_ctr[NGRP * 32];   // 128B-padded per group

static __device__ __forceinline__ unsigned long long pack2(float x, float y) {
    unsigned long long r;
    asm("mov.b64 %0, {%1, %2};" : "=l"(r) : "f"(x), "f"(y));
    return r;
}
static __device__ __forceinline__ void fma2(unsigned long long& d,
                                            unsigned long long a,
                                            unsigned long long b) {
    // Packed dual-FMA (Blackwell f32x2) — 2x FFMA throughput vs scalar.
    asm("fma.rn.f32x2 %0, %1, %2, %0;" : "+l"(d) : "l"(a), "l"(b));
}
static __device__ __forceinline__ float2 unpack2(unsigned long long v) {
    float lo, hi;
    asm("mov.b64 {%0, %1}, %2;" : "=f"(lo), "=f"(hi) : "l"(v));
    return make_float2(lo, hi);
}

// Zero the barrier counters before each run (graph replays reuse device globals).
__global__ void rnn_reset_kernel() {
    if (threadIdx.x < NGRP * 32) g_ctr[threadIdx.x] = 0u;
}

__global__ void __launch_bounds__(NTHREADS, 1)
rnn_persistent_kernel(const float* __restrict__ states,
                      const float* __restrict__ Wx,
                      const float* __restrict__ R,
                      const float* __restrict__ bias,
                      float* __restrict__ out)
{
    // Dynamic smem = 48KB: h panel (24KB, warp-private column slices) and red
    // spill scratch (24KB) are DISJOINT -> no sync between GEMM and spill
    // (spill rows are slice-private; the only ordering needed is S3 before
    // the cell reduce).
    extern __shared__ float smem[];
    float* h_sm = smem;                        // [GB][DD]           = 6144 floats
    float* red  = smem + GB * DD;              // [NSLICE][REDPITCH] = 6144 floats

    const int tid = threadIdx.x;
    const int grp = blockIdx.x >> 6;     // batch group 0/1
    const int cta = blockIdx.x & 63;     // CTA within group
    const int w   = tid >> 5;            // warp id (0..7)
    const int l   = tid & 31;            // lane
    const int hw  = l >> 4;              // half-warp -> k sub-slice
    const int c   = l & 15;              // column index (0..15)
    const int sl  = (w << 1) | hw;       // k-slice id (0..15)
    const int kb  = sl * KS;             // k base for this slice
    const int gcA = c;                   // 3 interleaved cols: gg = gc&3, dl = gc>>2
    const int gcB = c + 16;
    const int gcC = c + 32;
    const int d0  = cta * DPC;

    // ---- One-time: R slices for all 3 columns into registers (k-pair packed).
    unsigned long long RA[KS2], RB[KS2], RC[KS2];   // 144 registers
    {
        const float* RgA = R + (size_t)(gcA & 3) * DD * DD + (size_t)(d0 + (gcA >> 2));
        const float* RgB = R + (size_t)(gcB & 3) * DD * DD + (size_t)(d0 + (gcB >> 2));
        const float* RgC = R + (size_t)(gcC & 3) * DD * DD + (size_t)(d0 + (gcC >> 2));
        #pragma unroll
        for (int j = 0; j < KS2; ++j) {
            RA[j] = pack2(RgA[(size_t)(kb + 2 * j) * DD], RgA[(size_t)(kb + 2 * j + 1) * DD]);
            RB[j] = pack2(RgB[(size_t)(kb + 2 * j) * DD], RgB[(size_t)(kb + 2 * j + 1) * DD]);
            RC[j] = pack2(RgC[(size_t)(kb + 2 * j) * DD], RgC[(size_t)(kb + 2 * j + 1) * DD]);
        }
    }

    // ---- One-time: per-cell state (c) and t=0 output row. 96 cell threads.
    float c_state = 0.f;
    int gb = 0, cbl = 0, cd = 0;                  // global batch, local batch, local d
    if (tid < GB * DPC) {                         // 96 cells
        cbl = tid / DPC;
        cd  = tid - cbl * DPC;
        gb  = grp * GB + cbl;
        const int d = d0 + cd;
        const float h0 = states[(size_t)(0 * BB + gb) * DD + d];
        c_state        = states[(size_t)(1 * BB + gb) * DD + d];
        out[((size_t)(0 * BB + gb) * (TT + 1) + 0) * DD + d] = h0;
        out[((size_t)(1 * BB + gb) * (TT + 1) + 0) * DD + d] = c_state;
    }

    volatile unsigned* ctr = &g_ctr[grp * 32];

    // ---- Main recurrence ----
    for (int t = 0; t < TT; ++t) {
        // Phase 1: issue Wx(t) + bias loads early (consumed in cell phase).
        float wxi = 0.f, wxf = 0.f, wxz = 0.f, wxo = 0.f;
        if (tid < GB * DPC) {
            const int d = d0 + cd;
            const float* wp = Wx + ((size_t)gb * TT + t) * (NGATES * DD) + d;
            wxi = wp[0 * DD] + bias[0 * DD + d];
            wxf = wp[1 * DD] + bias[1 * DD + d];
            wxz = wp[2 * DD] + bias[2 * DD + d];
            wxo = wp[3 * DD] + bias[3 * DD + d];
        }

        // Phase 2: WARP-LOCAL h slice load — warp w owns k-cols [w*96,w*96+96)
        // of h_sm exclusively. 192 float4 per warp -> 6 per lane.
        {
            const float4* s4 = (const float4*)((t == 0) ? states : g_hbuf[t & 1])
                               + (size_t)grp * GB * (DD / 4);
            float4* d4 = (float4*)h_sm;
            #pragma unroll
            for (int r = 0; r < 6; ++r) {
                const int local = r * 32 + l;          // 0..191
                const int b  = local / 24;             // 24 float4 per k-slice row
                const int kq = local - b * 24;
                const int idx = b * (DD / 4) + w * 24 + kq;
                d4[idx] = s4[idx];
            }
            __syncwarp();
        }

        // Phase 3: GEMM. Half-warp owns 48-k slice; lane owns 3 gate columns.
        // One LDS.128 (4 h, half-warp broadcast) feeds 6 FFMA2.
        unsigned long long accA[GB], accB[GB], accC[GB];   // 48 registers
        #pragma unroll
        for (int b = 0; b < GB; ++b) { accA[b] = 0ull; accB[b] = 0ull; accC[b] = 0ull; }
        {
            const float* hk = h_sm + kb;
            #pragma unroll
            for (int j = 0; j < KS2; j += 2) {        // 12 iters, 4 k each
                #pragma unroll
                for (int b = 0; b < GB; ++b) {
                    const ulonglong2 hh =
                        *(const ulonglong2*)(hk + (size_t)b * DD + 2 * j);
                    fma2(accA[b], hh.x, RA[j]);
                    fma2(accA[b], hh.y, RA[j + 1]);
                    fma2(accB[b], hh.x, RB[j]);
                    fma2(accB[b], hh.y, RB[j + 1]);
                    fma2(accC[b], hh.x, RC[j]);
                    fma2(accC[b], hh.y, RC[j + 1]);
                }
            }
        }

        // Phase 4: spill per-slice partials red[sl][b*48+gc] (fold even/odd k).
        // red is disjoint from h_sm and slice-private -> NO sync needed first.
        {
            float* rw = red + (size_t)sl * REDPITCH;
            #pragma unroll
            for (int b = 0; b < GB; ++b) {
                const float2 vA = unpack2(accA[b]);
                const float2 vB = unpack2(accB[b]);
                const float2 vC = unpack2(accC[b]);
                rw[b * GC + gcA] = vA.x + vA.y;
                rw[b * GC + gcB] = vB.x + vB.y;
                rw[b * GC + gcC] = vC.x + vC.y;
            }
        }
        __syncthreads();   // S3: all spills visible

        // Phase 5+6 fused: cell threads reduce their 4 gates (one float4 per
        // slice, interleaved gc) and run the LSTM update.
        float hn = 0.f, cn = 0.f;
        if (tid < GB * DPC) {
            const int off = cbl * GC + cd * 4;        // gates i,f,z,o contiguous
            float4 g = make_float4(0.f, 0.f, 0.f, 0.f);
            #pragma unroll
            for (int ss = 0; ss < NSLICE; ++ss) {
                const float4 p = *(const float4*)(red + ss * REDPITCH + off);
                g.x += p.x; g.y += p.y; g.z += p.z; g.w += p.w;
            }
            const float gi = g.x + wxi;
            const float gf = g.y + wxf;
            const float gz = g.z + wxz;
            const float go = g.w + wxo;
            const float i_ = 1.f / (1.f + __expf(-gi));
            const float f_ = 1.f / (1.f + __expf(-gf));
            const float z_ = tanhf(gz);
            const float o_ = 1.f / (1.f + __expf(-go));
            cn = f_ * c_state + i_ * z_;
            hn = o_ * tanhf(cn);
            c_state = cn;
            g_hbuf[(t + 1) & 1][(size_t)gb * DD + d0 + cd] = hn;   // exchange
        }

        // Phase 7: PER-GROUP grid barrier (64 arrivals) — single monotonic
        // counter, ONE arriver + ONE poller per CTA (only proven-fast shape).
        __syncthreads();                   // S_flag: h writes issued by all cells
        if (tid == 0) {
            __threadfence();               // make h writes GPU-visible
            atomicAdd((unsigned*)ctr, 1u);
        }
        // Off-critical-path while waiting: out[] rows for t+1 (never read
        // cross-CTA).
        if (tid < GB * DPC) {
            const int d = d0 + cd;
            out[((size_t)(0 * BB + gb) * (TT + 1) + (t + 1)) * DD + d] = hn;
            out[((size_t)(1 * BB + gb) * (TT + 1) + (t + 1)) * DD + d] = cn;
        }
        if (tid == 0) {
            const unsigned target = (unsigned)(GCTAS) * (unsigned)(t + 1);
            while (*ctr < target) { }
            __threadfence();               // acquire
        }
        __syncthreads();                   // release whole CTA
    }
}

extern "C" void kernel_launch(void* const* d_in, const int* in_sizes, int n_in,
                              void* d_out, int out_size)
{
    const float* states = (const float*)d_in[0];  // [2,16,1,768]
    const float* Wx     = (const float*)d_in[1];  // [16,1024,4,1,768]
    const float* R      = (const float*)d_in[2];  // [4,1,768,768]
    const float* bias   = (const float*)d_in[3];  // [4,1,768]
    float*       out    = (float*)d_out;          // [2,16,1025,1,768]

    const size_t smem_bytes = (size_t)(GB * DD + NSLICE * REDPITCH) * sizeof(float); // 48KB

    rnn_reset_kernel<<<1, 64>>>();
    rnn_persistent_kernel<<<NCTA, NTHREADS, smem_bytes>>>(states, Wx, R, bias, out);
}

// round 12
// speedup vs baseline: 2.5335x; 1.0477x over previous
#include <cuda_runtime.h>
#include <cstdint>

// Problem constants — 2 independent batch groups x 64 CTAs = 128 SMs used
#define NGRP      2
#define GCTAS     64     // CTAs per group (all 128 co-resident on 148 SMs)
#define NCTA      (NGRP * GCTAS)
#define NTHREADS  256    // 8 warps — proven best shape
#define BB        16     // total batch
#define GB        8      // batches per group
#define HB        4      // batches per GEMM pass (register relief)
#define TT        1024   // time steps
#define DD        768    // hidden dim
#define NGATES    4
#define DPC       12     // d-columns per CTA (64*12 = 768)
#define GC        48     // gate columns per CTA (interleaved: gc = dl*4 + gate)
#define NSLICE    16     // k-slices = 8 warps x 2 half-warps
#define KS        48     // k per slice (16*48 = 768)
#define KS2       24     // packed f32x2 k-pairs per slice
#define REDPITCH  384    // floats per slice spill row (8 b x 48 gc)

// Global exchange state (device globals: no allocation anywhere)
__device__ __align__(16) float    g_hbuf[2][BB * DD];
__device__ unsigned               g_ctr[NGRP * 32];   // 128B-padded per group

static __device__ __forceinline__ unsigned long long pack2(float x, float y) {
    unsigned long long r;
    asm("mov.b64 %0, {%1, %2};" : "=l"(r) : "f"(x), "f"(y));
    return r;
}
static __device__ __forceinline__ void fma2(unsigned long long& d,
                                            unsigned long long a,
                                            unsigned long long b) {
    // Packed dual-FMA (Blackwell f32x2) — 2x FFMA throughput vs scalar.
    asm("fma.rn.f32x2 %0, %1, %2, %0;" : "+l"(d) : "l"(a), "l"(b));
}
static __device__ __forceinline__ float2 unpack2(unsigned long long v) {
    float lo, hi;
    asm("mov.b64 {%0, %1}, %2;" : "=f"(lo), "=f"(hi) : "l"(v));
    return make_float2(lo, hi);
}

// Zero the barrier counters before each run (graph replays reuse device globals).
__global__ void rnn_reset_kernel() {
    if (threadIdx.x < NGRP * 32) g_ctr[threadIdx.x] = 0u;
}

__global__ void __launch_bounds__(NTHREADS, 1)
rnn_persistent_kernel(const float* __restrict__ states,
                      const float* __restrict__ Wx,
                      const float* __restrict__ R,
                      const float* __restrict__ bias,
                      float* __restrict__ out)
{
    // Dynamic smem = 48KB: h panel (24KB, warp-private column slices) and red
    // spill scratch (24KB) are DISJOINT -> no sync between GEMM and spill.
    extern __shared__ float smem[];
    float* h_sm = smem;                        // [GB][DD]           = 6144 floats
    float* red  = smem + GB * DD;              // [NSLICE][REDPITCH] = 6144 floats

    const int tid = threadIdx.x;
    const int grp = blockIdx.x >> 6;     // batch group 0/1
    const int cta = blockIdx.x & 63;     // CTA within group
    const int w   = tid >> 5;            // warp id (0..7)
    const int l   = tid & 31;            // lane
    const int hw  = l >> 4;              // half-warp -> k sub-slice
    const int c   = l & 15;              // column index (0..15)
    const int sl  = (w << 1) | hw;       // k-slice id (0..15)
    const int kb  = sl * KS;             // k base for this slice
    const int gcA = c;                   // 3 interleaved cols: gg = gc&3, dl = gc>>2
    const int gcB = c + 16;
    const int gcC = c + 32;
    const int d0  = cta * DPC;

    // ---- One-time: R slices for all 3 columns into registers (k-pair packed).
    unsigned long long RA[KS2], RB[KS2], RC[KS2];   // 144 registers
    {
        const float* RgA = R + (size_t)(gcA & 3) * DD * DD + (size_t)(d0 + (gcA >> 2));
        const float* RgB = R + (size_t)(gcB & 3) * DD * DD + (size_t)(d0 + (gcB >> 2));
        const float* RgC = R + (size_t)(gcC & 3) * DD * DD + (size_t)(d0 + (gcC >> 2));
        #pragma unroll
        for (int j = 0; j < KS2; ++j) {
            RA[j] = pack2(RgA[(size_t)(kb + 2 * j) * DD], RgA[(size_t)(kb + 2 * j + 1) * DD]);
            RB[j] = pack2(RgB[(size_t)(kb + 2 * j) * DD], RgB[(size_t)(kb + 2 * j + 1) * DD]);
            RC[j] = pack2(RgC[(size_t)(kb + 2 * j) * DD], RgC[(size_t)(kb + 2 * j + 1) * DD]);
        }
    }

    // ---- One-time: per-cell state (c) and t=0 output row. 96 cell threads.
    float c_state = 0.f;
    int gb = 0, cbl = 0, cd = 0;                  // global batch, local batch, local d
    if (tid < GB * DPC) {                         // 96 cells
        cbl = tid / DPC;
        cd  = tid - cbl * DPC;
        gb  = grp * GB + cbl;
        const int d = d0 + cd;
        const float h0 = states[(size_t)(0 * BB + gb) * DD + d];
        c_state        = states[(size_t)(1 * BB + gb) * DD + d];
        out[((size_t)(0 * BB + gb) * (TT + 1) + 0) * DD + d] = h0;
        out[((size_t)(1 * BB + gb) * (TT + 1) + 0) * DD + d] = c_state;
    }

    volatile unsigned* ctr = &g_ctr[grp * 32];

    // ---- Main recurrence ----
    for (int t = 0; t < TT; ++t) {
        // Phase 1: issue Wx(t) + bias loads early (consumed in cell phase).
        float wxi = 0.f, wxf = 0.f, wxz = 0.f, wxo = 0.f;
        if (tid < GB * DPC) {
            const int d = d0 + cd;
            const float* wp = Wx + ((size_t)gb * TT + t) * (NGATES * DD) + d;
            wxi = wp[0 * DD] + bias[0 * DD + d];
            wxf = wp[1 * DD] + bias[1 * DD + d];
            wxz = wp[2 * DD] + bias[2 * DD + d];
            wxo = wp[3 * DD] + bias[3 * DD + d];
        }

        // Phase 2: WARP-LOCAL h slice load — warp w owns k-cols [w*96,w*96+96)
        // of h_sm exclusively. 192 float4 per warp -> 6 per lane.
        {
            const float4* s4 = (const float4*)((t == 0) ? states : g_hbuf[t & 1])
                               + (size_t)grp * GB * (DD / 4);
            float4* d4 = (float4*)h_sm;
            #pragma unroll
            for (int r = 0; r < 6; ++r) {
                const int local = r * 32 + l;          // 0..191
                const int b  = local / 24;             // 24 float4 per k-slice row
                const int kq = local - b * 24;
                const int idx = b * (DD / 4) + w * 24 + kq;
                d4[idx] = s4[idx];
            }
            __syncwarp();
        }

        // Phase 3/4: GEMM in TWO passes of 4 batches (acc = 24 regs instead of
        // 48 -> ~24 registers freed for hh load pipelining), each pass spilling
        // immediately (red disjoint + slice-private -> no sync needed).
        #pragma unroll
        for (int p = 0; p < 2; ++p) {
            unsigned long long accA[HB], accB[HB], accC[HB];   // 24 registers
            #pragma unroll
            for (int b = 0; b < HB; ++b) { accA[b] = 0ull; accB[b] = 0ull; accC[b] = 0ull; }
            {
                const float* hk = h_sm + (size_t)(p * HB) * DD + kb;
                #pragma unroll
                for (int j = 0; j < KS2; j += 2) {        // 12 iters, 4 k each
                    #pragma unroll
                    for (int b = 0; b < HB; ++b) {
                        const ulonglong2 hh =
                            *(const ulonglong2*)(hk + (size_t)b * DD + 2 * j);
                        fma2(accA[b], hh.x, RA[j]);
                        fma2(accA[b], hh.y, RA[j + 1]);
                        fma2(accB[b], hh.x, RB[j]);
                        fma2(accB[b], hh.y, RB[j + 1]);
                        fma2(accC[b], hh.x, RC[j]);
                        fma2(accC[b], hh.y, RC[j + 1]);
                    }
                }
            }
            {
                float* rw = red + (size_t)sl * REDPITCH + (size_t)(p * HB) * GC;
                #pragma unroll
                for (int b = 0; b < HB; ++b) {
                    const float2 vA = unpack2(accA[b]);
                    const float2 vB = unpack2(accB[b]);
                    const float2 vC = unpack2(accC[b]);
                    rw[b * GC + gcA] = vA.x + vA.y;
                    rw[b * GC + gcB] = vB.x + vB.y;
                    rw[b * GC + gcC] = vC.x + vC.y;
                }
            }
        }
        __syncthreads();   // S3: all spills visible

        // Phase 5+6 fused: cell threads reduce their 4 gates (one float4 per
        // slice, interleaved gc) and run the LSTM update.
        float hn = 0.f, cn = 0.f;
        if (tid < GB * DPC) {
            const int off = cbl * GC + cd * 4;        // gates i,f,z,o contiguous
            float4 g = make_float4(0.f, 0.f, 0.f, 0.f);
            #pragma unroll
            for (int ss = 0; ss < NSLICE; ++ss) {
                const float4 p = *(const float4*)(red + ss * REDPITCH + off);
                g.x += p.x; g.y += p.y; g.z += p.z; g.w += p.w;
            }
            const float gi = g.x + wxi;
            const float gf = g.y + wxf;
            const float gz = g.z + wxz;
            const float go = g.w + wxo;
            const float i_ = 1.f / (1.f + __expf(-gi));
            const float f_ = 1.f / (1.f + __expf(-gf));
            const float z_ = tanhf(gz);
            const float o_ = 1.f / (1.f + __expf(-go));
            cn = f_ * c_state + i_ * z_;
            hn = o_ * tanhf(cn);
            c_state = cn;
            g_hbuf[(t + 1) & 1][(size_t)gb * DD + d0 + cd] = hn;   // exchange
        }

        // Phase 7: PER-GROUP grid barrier (64 arrivals) — single monotonic
        // counter, ONE arriver + ONE poller per CTA (only proven-fast shape).
        __syncthreads();                   // S_flag: h writes issued by all cells
        if (tid == 0) {
            __threadfence();               // make h writes GPU-visible
            atomicAdd((unsigned*)ctr, 1u);
        }
        // Off-critical-path while waiting: out[] rows for t+1 (never read
        // cross-CTA).
        if (tid < GB * DPC) {
            const int d = d0 + cd;
            out[((size_t)(0 * BB + gb) * (TT + 1) + (t + 1)) * DD + d] = hn;
            out[((size_t)(1 * BB + gb) * (TT + 1) + (t + 1)) * DD + d] = cn;
        }
        if (tid == 0) {
            const unsigned target = (unsigned)(GCTAS) * (unsigned)(t + 1);
            while (*ctr < target) { }
            __threadfence();               // acquire
        }
        __syncthreads();                   // release whole CTA
    }
}

extern "C" void kernel_launch(void* const* d_in, const int* in_sizes, int n_in,
                              void* d_out, int out_size)
{
    const float* states = (const float*)d_in[0];  // [2,16,1,768]
    const float* Wx     = (const float*)d_in[1];  // [16,1024,4,1,768]
    const float* R      = (const float*)d_in[2];  // [4,1,768,768]
    const float* bias   = (const float*)d_in[3];  // [4,1,768]
    float*       out    = (float*)d_out;          // [2,16,1025,1,768]

    const size_t smem_bytes = (size_t)(GB * DD + NSLICE * REDPITCH) * sizeof(float); // 48KB

    rnn_reset_kernel<<<1, 64>>>();
    rnn_persistent_kernel<<<NCTA, NTHREADS, smem_bytes>>>(states, Wx, R, bias, out);
}

// round 13
// speedup vs baseline: 2.5399x; 1.0025x over previous
#include <cuda_runtime.h>
#include <cstdint>

// Problem constants — 2 independent batch groups x 64 CTAs = 128 SMs used
#define NGRP      2
#define GCTAS     64     // CTAs per group (all 128 co-resident on 148 SMs)
#define NCTA      (NGRP * GCTAS)
#define NTHREADS  256    // 8 warps — proven best shape
#define BB        16     // total batch
#define GB        8      // batches per group
#define HB        4      // batches per GEMM pass (register relief)
#define TT        1024   // time steps
#define DD        768    // hidden dim
#define NGATES    4
#define DPC       12     // d-columns per CTA (64*12 = 768)
#define GC        48     // gate columns per CTA (interleaved: gc = dl*4 + gate)
#define NSLICE    16     // k-slices = 8 warps x 2 half-warps
#define KS        48     // k per slice (16*48 = 768)
#define KS2       24     // packed f32x2 k-pairs per slice
#define REDPITCH  384    // floats per slice spill row (8 b x 48 gc)

// Global exchange state (device globals: no allocation anywhere)
__device__ __align__(16) float    g_hbuf[2][BB * DD];
__device__ unsigned               g_ctr[NGRP * 32];   // 128B-padded per group

static __device__ __forceinline__ unsigned long long pack2(float x, float y) {
    unsigned long long r;
    asm("mov.b64 %0, {%1, %2};" : "=l"(r) : "f"(x), "f"(y));
    return r;
}
static __device__ __forceinline__ void fma2(unsigned long long& d,
                                            unsigned long long a,
                                            unsigned long long b) {
    // Packed dual-FMA (Blackwell f32x2) — 2x FFMA throughput vs scalar.
    asm("fma.rn.f32x2 %0, %1, %2, %0;" : "+l"(d) : "l"(a), "l"(b));
}
static __device__ __forceinline__ float2 unpack2(unsigned long long v) {
    float lo, hi;
    asm("mov.b64 {%0, %1}, %2;" : "=f"(lo), "=f"(hi) : "l"(v));
    return make_float2(lo, hi);
}
// L1-bypassing float4 load: always observes L2 (no stale double-buffer lines),
// which makes the acquire-side __threadfence (and its CCTL.IVALL L1-flush)
// unnecessary on the consumer path.
static __device__ __forceinline__ float4 ldg_cv_f4(const float4* p) {
    float4 v;
    asm volatile("ld.global.cv.v4.f32 {%0,%1,%2,%3}, [%4];"
                 : "=f"(v.x), "=f"(v.y), "=f"(v.z), "=f"(v.w) : "l"(p));
    return v;
}

// Zero the barrier counters before each run (graph replays reuse device globals).
__global__ void rnn_reset_kernel() {
    if (threadIdx.x < NGRP * 32) g_ctr[threadIdx.x] = 0u;
}

__global__ void __launch_bounds__(NTHREADS, 1)
rnn_persistent_kernel(const float* __restrict__ states,
                      const float* __restrict__ Wx,
                      const float* __restrict__ R,
                      const float* __restrict__ bias,
                      float* __restrict__ out)
{
    // Dynamic smem = 48KB: h panel (24KB, warp-private column slices) and red
    // spill scratch (24KB) are DISJOINT -> no sync between GEMM and spill.
    extern __shared__ float smem[];
    float* h_sm = smem;                        // [GB][DD]           = 6144 floats
    float* red  = smem + GB * DD;              // [NSLICE][REDPITCH] = 6144 floats

    const int tid = threadIdx.x;
    const int grp = blockIdx.x >> 6;     // batch group 0/1
    const int cta = blockIdx.x & 63;     // CTA within group
    const int w   = tid >> 5;            // warp id (0..7)
    const int l   = tid & 31;            // lane
    const int hw  = l >> 4;              // half-warp -> k sub-slice
    const int c   = l & 15;              // column index (0..15)
    const int sl  = (w << 1) | hw;       // k-slice id (0..15)
    const int kb  = sl * KS;             // k base for this slice
    const int gcA = c;                   // 3 interleaved cols: gg = gc&3, dl = gc>>2
    const int gcB = c + 16;
    const int gcC = c + 32;
    const int d0  = cta * DPC;

    // ---- One-time: R slices for all 3 columns into registers (k-pair packed).
    unsigned long long RA[KS2], RB[KS2], RC[KS2];   // 144 registers
    {
        const float* RgA = R + (size_t)(gcA & 3) * DD * DD + (size_t)(d0 + (gcA >> 2));
        const float* RgB = R + (size_t)(gcB & 3) * DD * DD + (size_t)(d0 + (gcB >> 2));
        const float* RgC = R + (size_t)(gcC & 3) * DD * DD + (size_t)(d0 + (gcC >> 2));
        #pragma unroll
        for (int j = 0; j < KS2; ++j) {
            RA[j] = pack2(RgA[(size_t)(kb + 2 * j) * DD], RgA[(size_t)(kb + 2 * j + 1) * DD]);
            RB[j] = pack2(RgB[(size_t)(kb + 2 * j) * DD], RgB[(size_t)(kb + 2 * j + 1) * DD]);
            RC[j] = pack2(RgC[(size_t)(kb + 2 * j) * DD], RgC[(size_t)(kb + 2 * j + 1) * DD]);
        }
    }

    // ---- One-time: per-cell state (c) and t=0 output row. 96 cell threads.
    float c_state = 0.f;
    int gb = 0, cbl = 0, cd = 0;                  // global batch, local batch, local d
    if (tid < GB * DPC) {                         // 96 cells
        cbl = tid / DPC;
        cd  = tid - cbl * DPC;
        gb  = grp * GB + cbl;
        const int d = d0 + cd;
        const float h0 = states[(size_t)(0 * BB + gb) * DD + d];
        c_state        = states[(size_t)(1 * BB + gb) * DD + d];
        out[((size_t)(0 * BB + gb) * (TT + 1) + 0) * DD + d] = h0;
        out[((size_t)(1 * BB + gb) * (TT + 1) + 0) * DD + d] = c_state;
    }

    volatile unsigned* ctr = &g_ctr[grp * 32];

    // ---- Main recurrence ----
    for (int t = 0; t < TT; ++t) {
        // Phase 1: issue Wx(t) + bias loads early (consumed in cell phase).
        float wxi = 0.f, wxf = 0.f, wxz = 0.f, wxo = 0.f;
        if (tid < GB * DPC) {
            const int d = d0 + cd;
            const float* wp = Wx + ((size_t)gb * TT + t) * (NGATES * DD) + d;
            wxi = wp[0 * DD] + bias[0 * DD + d];
            wxf = wp[1 * DD] + bias[1 * DD + d];
            wxz = wp[2 * DD] + bias[2 * DD + d];
            wxo = wp[3 * DD] + bias[3 * DD + d];
        }

        // Phase 2: WARP-LOCAL h slice load (L1-bypass cv) — warp w owns k-cols
        // [w*96,w*96+96) of h_sm exclusively. 192 float4 per warp -> 6 per lane.
        {
            const float4* s4 = (const float4*)((t == 0) ? states : g_hbuf[t & 1])
                               + (size_t)grp * GB * (DD / 4);
            float4* d4 = (float4*)h_sm;
            #pragma unroll
            for (int r = 0; r < 6; ++r) {
                const int local = r * 32 + l;          // 0..191
                const int b  = local / 24;             // 24 float4 per k-slice row
                const int kq = local - b * 24;
                const int idx = b * (DD / 4) + w * 24 + kq;
                d4[idx] = ldg_cv_f4(s4 + idx);
            }
            __syncwarp();
        }

        // Phase 3/4: GEMM in TWO passes of 4 batches (acc = 24 regs -> deep
        // hh load pipelining), each pass spilling immediately (red disjoint +
        // slice-private -> no sync needed).
        #pragma unroll
        for (int p = 0; p < 2; ++p) {
            unsigned long long accA[HB], accB[HB], accC[HB];   // 24 registers
            #pragma unroll
            for (int b = 0; b < HB; ++b) { accA[b] = 0ull; accB[b] = 0ull; accC[b] = 0ull; }
            {
                const float* hk = h_sm + (size_t)(p * HB) * DD + kb;
                #pragma unroll
                for (int j = 0; j < KS2; j += 2) {        // 12 iters, 4 k each
                    #pragma unroll
                    for (int b = 0; b < HB; ++b) {
                        const ulonglong2 hh =
                            *(const ulonglong2*)(hk + (size_t)b * DD + 2 * j);
                        fma2(accA[b], hh.x, RA[j]);
                        fma2(accA[b], hh.y, RA[j + 1]);
                        fma2(accB[b], hh.x, RB[j]);
                        fma2(accB[b], hh.y, RB[j + 1]);
                        fma2(accC[b], hh.x, RC[j]);
                        fma2(accC[b], hh.y, RC[j + 1]);
                    }
                }
            }
            {
                float* rw = red + (size_t)sl * REDPITCH + (size_t)(p * HB) * GC;
                #pragma unroll
                for (int b = 0; b < HB; ++b) {
                    const float2 vA = unpack2(accA[b]);
                    const float2 vB = unpack2(accB[b]);
                    const float2 vC = unpack2(accC[b]);
                    rw[b * GC + gcA] = vA.x + vA.y;
                    rw[b * GC + gcB] = vB.x + vB.y;
                    rw[b * GC + gcC] = vC.x + vC.y;
                }
            }
        }
        __syncthreads();   // S3: all spills visible

        // Phase 5+6 fused: cell threads reduce their 4 gates (one float4 per
        // slice, interleaved gc) and run the LSTM update.
        float hn = 0.f, cn = 0.f;
        if (tid < GB * DPC) {
            const int off = cbl * GC + cd * 4;        // gates i,f,z,o contiguous
            float4 g = make_float4(0.f, 0.f, 0.f, 0.f);
            #pragma unroll
            for (int ss = 0; ss < NSLICE; ++ss) {
                const float4 p = *(const float4*)(red + ss * REDPITCH + off);
                g.x += p.x; g.y += p.y; g.z += p.z; g.w += p.w;
            }
            const float gi = g.x + wxi;
            const float gf = g.y + wxf;
            const float gz = g.z + wxz;
            const float go = g.w + wxo;
            const float i_ = 1.f / (1.f + __expf(-gi));
            const float f_ = 1.f / (1.f + __expf(-gf));
            const float z_ = tanhf(gz);
            const float o_ = 1.f / (1.f + __expf(-go));
            cn = f_ * c_state + i_ * z_;
            hn = o_ * tanhf(cn);
            c_state = cn;
            g_hbuf[(t + 1) & 1][(size_t)gb * DD + d0 + cd] = hn;   // exchange
        }

        // Phase 7: PER-GROUP barrier.
        // Arrive: S_flag syncthreads orders all red-reads + h-stores of this
        // CTA, then ONE fence + ONE atomicAdd (proven shape).
        // Release: PER-WARP — lane 0 spins on the counter (volatile, L2 read-
        // shared), __syncwarp, go. No final __syncthreads, no acquire fence
        // (h consumers use .cv loads). Safe because h_sm slices and red rows
        // are warp-private, and a CTA's arrival (post-S_flag) already implies
        // its cell warps finished reading red / writing h.
        __syncthreads();                   // S_flag
        if (tid == 0) {
            __threadfence();               // order h stores before the arrive
            atomicAdd((unsigned*)ctr, 1u);
        }
        // Off-critical-path: out[] rows for t+1 (never read cross-CTA).
        if (tid < GB * DPC) {
            const int d = d0 + cd;
            out[((size_t)(0 * BB + gb) * (TT + 1) + (t + 1)) * DD + d] = hn;
            out[((size_t)(1 * BB + gb) * (TT + 1) + (t + 1)) * DD + d] = cn;
        }
        {
            const unsigned target = (unsigned)(GCTAS) * (unsigned)(t + 1);
            if (l == 0) {
                while (*ctr < target) { }
            }
            __syncwarp();                  // warp proceeds independently
        }
    }
}

extern "C" void kernel_launch(void* const* d_in, const int* in_sizes, int n_in,
                              void* d_out, int out_size)
{
    const float* states = (const float*)d_in[0];  // [2,16,1,768]
    const float* Wx     = (const float*)d_in[1];  // [16,1024,4,1,768]
    const float* R      = (const float*)d_in[2];  // [4,1,768,768]
    const float* bias   = (const float*)d_in[3];  // [4,1,768]
    float*       out    = (float*)d_out;          // [2,16,1025,1,768]

    const size_t smem_bytes = (size_t)(GB * DD + NSLICE * REDPITCH) * sizeof(float); // 48KB

    rnn_reset_kernel<<<1, 64>>>();
    rnn_persistent_kernel<<<NCTA, NTHREADS, smem_bytes>>>(states, Wx, R, bias, out);
}